// round 1
// baseline (speedup 1.0000x reference)
#include <cuda_runtime.h>
#include <cstdint>
#include <cstddef>

#define BB 64
#define TT 512
#define DD 256
#define GG 1024   // 4*D

// ---------------- scratch (device globals; no runtime allocation) ----------
__device__ float d_xs[(size_t)BB * TT * GG];    // 134 MB: per-step input pre-activations
__device__ float d_h[(size_t)BB * TT * DD];     // 33.5 MB: all hidden states
__device__ float d_snorm[BB * DD];
__device__ float d_whhT[DD * GG];               // w_hh transposed: [d][j]
__device__ float d_WpT[DD * DD];
__device__ float d_WxT[DD * DD];
__device__ float d_WfT[DD * DD];
__device__ float d_z[BB * TT];
__device__ float d_r[BB * DD];

__device__ __forceinline__ float sigf(float x) { return 1.f / (1.f + expf(-x)); }

// ---------------- prep: transposes for coalesced access --------------------
__global__ void k_prep(const float* __restrict__ w_hh, const float* __restrict__ W_p,
                       const float* __restrict__ W_x, const float* __restrict__ W_f) {
    int i = blockIdx.x * 256 + threadIdx.x;
    if (i < GG * DD) { int j = i / DD, d = i % DD; d_whhT[d * GG + j] = w_hh[i]; }
    if (i < DD * DD) {
        int e = i / DD, d = i % DD;
        d_WpT[d * DD + e] = W_p[i];
        d_WxT[d * DD + e] = W_x[i];
        d_WfT[d * DD + e] = W_f[i];
    }
}

// ---------------- s_norm: batch-norm of query embeddings --------------------
__global__ void k_snorm(const int* __restrict__ s, const float* __restrict__ emb) {
    int d = threadIdx.x;  // 256 threads
    float sum = 0.f, sq = 0.f;
    for (int b = 0; b < BB; b++) {
        float v = emb[(size_t)s[b] * DD + d];
        sum += v; sq += v * v;
    }
    float mu  = sum * (1.f / BB);
    float var = sq * (1.f / BB) - mu * mu;
    float inv = rsqrtf(var + 1e-5f);
    for (int b = 0; b < BB; b++) {
        float v = emb[(size_t)s[b] * DD + d];
        d_snorm[b * DD + d] = (v - mu) * inv;
    }
}

// ---------------- xs = emb[x] @ w_ih.T + b_lstm  (gather GEMM) --------------
// C[M=32768, N=1024], K=256.  Tile 64x64, k-tile 16, 256 threads, 4x4 micro.
__global__ void __launch_bounds__(256) k_xs(const int* __restrict__ x,
                                            const float* __restrict__ emb,
                                            const float* __restrict__ w_ih,
                                            const float* __restrict__ bl) {
    __shared__ float As[16][64];
    __shared__ float Bs[16][64];
    int tid = threadIdx.x;
    int m0 = blockIdx.x * 64, n0 = blockIdx.y * 64;
    int tx = tid % 16, ty = tid / 16;
    int lr = tid / 4, lk = (tid % 4) * 4;

    int tok = x[m0 + lr];
    const float* arow = emb + (size_t)tok * DD;
    const float* brow = w_ih + (size_t)(n0 + lr) * DD;

    float acc[4][4];
#pragma unroll
    for (int i = 0; i < 4; i++)
#pragma unroll
        for (int j = 0; j < 4; j++) acc[i][j] = 0.f;

    for (int k0 = 0; k0 < DD; k0 += 16) {
        float4 av = *(const float4*)(arow + k0 + lk);
        float4 bv = *(const float4*)(brow + k0 + lk);
        As[lk + 0][lr] = av.x; As[lk + 1][lr] = av.y;
        As[lk + 2][lr] = av.z; As[lk + 3][lr] = av.w;
        Bs[lk + 0][lr] = bv.x; Bs[lk + 1][lr] = bv.y;
        Bs[lk + 2][lr] = bv.z; Bs[lk + 3][lr] = bv.w;
        __syncthreads();
#pragma unroll
        for (int k = 0; k < 16; k++) {
            float4 a = *(const float4*)&As[k][ty * 4];
            float4 b = *(const float4*)&Bs[k][tx * 4];
            float aa[4] = {a.x, a.y, a.z, a.w};
            float bb[4] = {b.x, b.y, b.z, b.w};
#pragma unroll
            for (int i = 0; i < 4; i++)
#pragma unroll
                for (int j = 0; j < 4; j++) acc[i][j] += aa[i] * bb[j];
        }
        __syncthreads();
    }
#pragma unroll
    for (int i = 0; i < 4; i++) {
        size_t row = m0 + ty * 4 + i;
#pragma unroll
        for (int j = 0; j < 4; j++) {
            int col = n0 + tx * 4 + j;
            d_xs[row * GG + col] = acc[i][j] + bl[col];
        }
    }
}

// ---------------- LSTM recurrence: 32 CTAs x 2 batches each -----------------
__global__ void __launch_bounds__(256) k_lstm() {
    int b0 = blockIdx.x * 2;
    __shared__ float hs[2][DD];
    __shared__ float cs[2][DD];
    __shared__ float gt[2][GG];
    int tid = threadIdx.x;
    hs[0][tid] = 0.f; hs[1][tid] = 0.f;
    cs[0][tid] = 0.f; cs[1][tid] = 0.f;
    __syncthreads();

    const float* xs0 = d_xs + (size_t)b0 * TT * GG;
    const float* xs1 = d_xs + (size_t)(b0 + 1) * TT * GG;

    for (int t = 0; t < TT; t++) {
        // gate pre-activations: thread computes j = 4*tid..4*tid+3 for both batches
        float4 a0 = *(const float4*)(xs0 + (size_t)t * GG + 4 * tid);
        float4 a1 = *(const float4*)(xs1 + (size_t)t * GG + 4 * tid);
#pragma unroll 4
        for (int d = 0; d < DD; d++) {
            float4 w = *(const float4*)(d_whhT + d * GG + 4 * tid);
            float h0 = hs[0][d], h1 = hs[1][d];
            a0.x += w.x * h0; a0.y += w.y * h0; a0.z += w.z * h0; a0.w += w.w * h0;
            a1.x += w.x * h1; a1.y += w.y * h1; a1.z += w.z * h1; a1.w += w.w * h1;
        }
        *(float4*)&gt[0][4 * tid] = a0;
        *(float4*)&gt[1][4 * tid] = a1;
        __syncthreads();
#pragma unroll
        for (int bb = 0; bb < 2; bb++) {
            float ig = sigf(gt[bb][tid]);
            float fg = sigf(gt[bb][DD + tid]);
            float g2 = tanhf(gt[bb][2 * DD + tid]);
            float og = sigf(gt[bb][3 * DD + tid]);
            float c = fg * cs[bb][tid] + ig * g2;
            float h = og * tanhf(c);
            cs[bb][tid] = c;
            hs[bb][tid] = h;
            d_h[((size_t)(b0 + bb) * TT + t) * DD + tid] = h;
        }
        __syncthreads();
    }
}

// ---- correlation m + Y = tanh(m@W_y) + z = Y . w_t  (fused) ----------------
// grid (b=64, tblk=16): each CTA handles 32 timesteps of one batch element.
__global__ void __launch_bounds__(256) k_att(const float* __restrict__ W_y,
                                             const float* __restrict__ w_t) {
    int b = blockIdx.x;
    int t0 = blockIdx.y * 32;
    int tid = threadIdx.x;
    __shared__ float sdup[2 * DD];
    __shared__ float buf[32][DD];   // holds h rows, then reused for m rows
    __shared__ float zpart[8][32];

    sdup[tid] = d_snorm[b * DD + tid];
    sdup[DD + tid] = d_snorm[b * DD + tid];
    for (int r = 0; r < 32; r++)
        buf[r][tid] = d_h[((size_t)b * TT + t0 + r) * DD + tid];
    __syncthreads();

    // m[r][n=tid] = sum_d h[r][d] * s_norm[(d+n)%D]
    float mm[32];
#pragma unroll
    for (int r = 0; r < 32; r++) mm[r] = 0.f;
    for (int d = 0; d < DD; d++) {
        float sv = sdup[d + tid];
#pragma unroll
        for (int r = 0; r < 32; r++) mm[r] += buf[r][d] * sv;
    }
    __syncthreads();
#pragma unroll
    for (int r = 0; r < 32; r++) buf[r][tid] = mm[r];
    __syncthreads();

    // Y[r][e=tid] = sum_d m[r][d] * W_y[d][e];  z[r] = sum_e tanh(Y)*w_t[e]
    float wt = w_t[tid];
#pragma unroll
    for (int r = 0; r < 32; r++) mm[r] = 0.f;
    for (int d = 0; d < DD; d++) {
        float w = W_y[d * DD + tid];
#pragma unroll
        for (int r = 0; r < 32; r++) mm[r] += buf[r][d] * w;
    }
    int lane = tid & 31, wrp = tid >> 5;
#pragma unroll
    for (int r = 0; r < 32; r++) {
        float v = tanhf(mm[r]) * wt;
        v += __shfl_down_sync(0xffffffffu, v, 16);
        v += __shfl_down_sync(0xffffffffu, v, 8);
        v += __shfl_down_sync(0xffffffffu, v, 4);
        v += __shfl_down_sync(0xffffffffu, v, 2);
        v += __shfl_down_sync(0xffffffffu, v, 1);
        if (lane == 0) zpart[wrp][r] = v;
    }
    __syncthreads();
    if (tid < 32) {
        float sacc = 0.f;
#pragma unroll
        for (int w = 0; w < 8; w++) sacc += zpart[w][tid];
        d_z[b * TT + t0 + tid] = sacc;
    }
}

// ---- softmax over T and r = sum_t a[t]*h[t]  --------------------------------
__global__ void __launch_bounds__(256) k_soft_r() {
    int b = blockIdx.x, tid = threadIdx.x;
    __shared__ float zsh[TT];
    __shared__ float red[256];
    zsh[tid] = d_z[b * TT + tid];
    zsh[256 + tid] = d_z[b * TT + 256 + tid];
    __syncthreads();
    float lm = fmaxf(zsh[tid], zsh[tid + 256]);
    red[tid] = lm; __syncthreads();
    for (int s = 128; s > 0; s >>= 1) {
        if (tid < s) red[tid] = fmaxf(red[tid], red[tid + s]);
        __syncthreads();
    }
    float mx = red[0]; __syncthreads();
    float e0 = expf(zsh[tid] - mx), e1 = expf(zsh[tid + 256] - mx);
    red[tid] = e0 + e1; __syncthreads();
    for (int s = 128; s > 0; s >>= 1) {
        if (tid < s) red[tid] += red[tid + s];
        __syncthreads();
    }
    float inv = 1.f / red[0]; __syncthreads();
    zsh[tid] = e0 * inv;
    zsh[tid + 256] = e1 * inv;
    __syncthreads();
    float acc = 0.f;
    const float* hb = d_h + (size_t)b * TT * DD;
    for (int t = 0; t < TT; t++) acc += zsh[t] * hb[(size_t)t * DD + tid];
    d_r[b * DD + tid] = acc;
}

// ---- final head: rr = tanh(r@Wp.T + h_last@Wx.T); y = softmax(rr@Wf.T + b_f)
__global__ void __launch_bounds__(256) k_final(const float* __restrict__ b_f,
                                               float* __restrict__ out) {
    int b = blockIdx.x, tid = threadIdx.x;
    __shared__ float rsh[DD], hls[DD], rrsh[DD], red[256];
    rsh[tid] = d_r[b * DD + tid];
    hls[tid] = d_h[((size_t)b * TT + (TT - 1)) * DD + tid];
    __syncthreads();
    float acc = 0.f;
    for (int d = 0; d < DD; d++)
        acc += rsh[d] * d_WpT[d * DD + tid] + hls[d] * d_WxT[d * DD + tid];
    rrsh[tid] = tanhf(acc);
    __syncthreads();
    float lg = b_f[tid];
    for (int e = 0; e < DD; e++) lg += rrsh[e] * d_WfT[e * DD + tid];
    red[tid] = lg; __syncthreads();
    for (int s = 128; s > 0; s >>= 1) {
        if (tid < s) red[tid] = fmaxf(red[tid], red[tid + s]);
        __syncthreads();
    }
    float mx = red[0]; __syncthreads();
    float ex = expf(lg - mx);
    red[tid] = ex; __syncthreads();
    for (int s = 128; s > 0; s >>= 1) {
        if (tid < s) red[tid] += red[tid + s];
        __syncthreads();
    }
    out[b * DD + tid] = ex / red[0];
}

// ---------------------------------------------------------------------------
extern "C" void kernel_launch(void* const* d_in, const int* in_sizes, int n_in,
                              void* d_out, int out_size) {
    const int*   x      = (const int*)d_in[0];
    const int*   s      = (const int*)d_in[1];
    const float* emb    = (const float*)d_in[2];
    const float* w_ih   = (const float*)d_in[3];
    const float* w_hh   = (const float*)d_in[4];
    const float* b_lstm = (const float*)d_in[5];
    const float* W_y    = (const float*)d_in[6];
    const float* w_t    = (const float*)d_in[7];
    const float* W_p    = (const float*)d_in[8];
    const float* W_x    = (const float*)d_in[9];
    const float* W_f    = (const float*)d_in[10];
    const float* b_f    = (const float*)d_in[11];
    float* out = (float*)d_out;

    k_prep<<<1024, 256>>>(w_hh, W_p, W_x, W_f);
    k_snorm<<<1, 256>>>(s, emb);
    k_xs<<<dim3(512, 16), 256>>>(x, emb, w_ih, b_lstm);
    k_lstm<<<32, 256>>>();
    k_att<<<dim3(64, 16), 256>>>(W_y, w_t);
    k_soft_r<<<64, 256>>>();
    k_final<<<64, 256>>>(b_f, out);
}

// round 3
// speedup vs baseline: 4.1937x; 4.1937x over previous
#include <cuda_runtime.h>
#include <cstdint>
#include <cstddef>

#define BB 64
#define TT 512
#define DD 256
#define GG 1024   // 4*D
#define CLS 8     // CTAs per cluster
#define BPC 4     // batches per cluster

// ---------------- scratch (device globals; no runtime allocation) ----------
__device__ float d_xs[(size_t)BB * TT * GG];    // per-step input pre-activations
__device__ float d_h[(size_t)BB * TT * DD];     // all hidden states
__device__ float d_snorm[BB * DD];
__device__ float d_WpT[DD * DD];
__device__ float d_WxT[DD * DD];
__device__ float d_WfT[DD * DD];
__device__ float d_z[BB * TT];
__device__ float d_r[BB * DD];

__device__ __forceinline__ float sigf(float x) { return 1.f / (1.f + expf(-x)); }

__device__ __forceinline__ uint32_t ctarank() {
    uint32_t r; asm("mov.u32 %0, %%cluster_ctarank;" : "=r"(r)); return r;
}
__device__ __forceinline__ void cluster_sync() {
    asm volatile("barrier.cluster.arrive.aligned;\n\tbarrier.cluster.wait.aligned;" ::: "memory");
}
__device__ __forceinline__ uint32_t mapa_sh(uint32_t laddr, uint32_t rank) {
    uint32_t ra; asm("mapa.shared::cluster.u32 %0, %1, %2;" : "=r"(ra) : "r"(laddr), "r"(rank));
    return ra;
}
__device__ __forceinline__ void sts_cluster(uint32_t raddr, float v) {
    asm volatile("st.shared::cluster.f32 [%0], %1;" :: "r"(raddr), "f"(v) : "memory");
}

// ---------------- prep: transposes for coalesced access --------------------
__global__ void k_prep(const float* __restrict__ W_p,
                       const float* __restrict__ W_x, const float* __restrict__ W_f) {
    int i = blockIdx.x * 256 + threadIdx.x;
    if (i < DD * DD) {
        int e = i / DD, d = i % DD;
        d_WpT[d * DD + e] = W_p[i];
        d_WxT[d * DD + e] = W_x[i];
        d_WfT[d * DD + e] = W_f[i];
    }
}

// ---------------- s_norm: batch-norm of query embeddings --------------------
__global__ void k_snorm(const int* __restrict__ s, const float* __restrict__ emb) {
    int d = threadIdx.x;  // 256 threads
    float sum = 0.f, sq = 0.f;
    for (int b = 0; b < BB; b++) {
        float v = emb[(size_t)s[b] * DD + d];
        sum += v; sq += v * v;
    }
    float mu  = sum * (1.f / BB);
    float var = sq * (1.f / BB) - mu * mu;
    float inv = rsqrtf(var + 1e-5f);
    for (int b = 0; b < BB; b++) {
        float v = emb[(size_t)s[b] * DD + d];
        d_snorm[b * DD + d] = (v - mu) * inv;
    }
}

// ---------------- xs = emb[x] @ w_ih.T + b_lstm  (gather GEMM) --------------
__global__ void __launch_bounds__(256) k_xs(const int* __restrict__ x,
                                            const float* __restrict__ emb,
                                            const float* __restrict__ w_ih,
                                            const float* __restrict__ bl) {
    __shared__ float As[16][64];
    __shared__ float Bs[16][64];
    int tid = threadIdx.x;
    int m0 = blockIdx.x * 64, n0 = blockIdx.y * 64;
    int tx = tid % 16, ty = tid / 16;
    int lr = tid / 4, lk = (tid % 4) * 4;

    int tok = x[m0 + lr];
    const float* arow = emb + (size_t)tok * DD;
    const float* brow = w_ih + (size_t)(n0 + lr) * DD;

    float acc[4][4];
#pragma unroll
    for (int i = 0; i < 4; i++)
#pragma unroll
        for (int j = 0; j < 4; j++) acc[i][j] = 0.f;

    for (int k0 = 0; k0 < DD; k0 += 16) {
        float4 av = *(const float4*)(arow + k0 + lk);
        float4 bv = *(const float4*)(brow + k0 + lk);
        As[lk + 0][lr] = av.x; As[lk + 1][lr] = av.y;
        As[lk + 2][lr] = av.z; As[lk + 3][lr] = av.w;
        Bs[lk + 0][lr] = bv.x; Bs[lk + 1][lr] = bv.y;
        Bs[lk + 2][lr] = bv.z; Bs[lk + 3][lr] = bv.w;
        __syncthreads();
#pragma unroll
        for (int k = 0; k < 16; k++) {
            float4 a = *(const float4*)&As[k][ty * 4];
            float4 b = *(const float4*)&Bs[k][tx * 4];
            float aa[4] = {a.x, a.y, a.z, a.w};
            float bb[4] = {b.x, b.y, b.z, b.w};
#pragma unroll
            for (int i = 0; i < 4; i++)
#pragma unroll
                for (int j = 0; j < 4; j++) acc[i][j] += aa[i] * bb[j];
        }
        __syncthreads();
    }
#pragma unroll
    for (int i = 0; i < 4; i++) {
        size_t row = m0 + ty * 4 + i;
#pragma unroll
        for (int j = 0; j < 4; j++) {
            int col = n0 + tx * 4 + j;
            d_xs[row * GG + col] = acc[i][j] + bl[col];
        }
    }
}

// ---------------- LSTM recurrence: cluster-parallel -------------------------
// 16 clusters x 8 CTAs. Cluster c owns batches [4c,4c+4). CTA rank r owns
// d-slice [32r,32r+32) => gate rows {g*256+32r+i}. Weights SMEM-resident.
// h exchanged each step via DSMEM pushes + one cluster barrier.
__global__ void __launch_bounds__(256, 1) __cluster_dims__(CLS, 1, 1)
k_lstm2(const float* __restrict__ w_hh) {
    extern __shared__ float smem[];
    float* wsm = smem;                    // [256 d][128 jl]
    float* psm = smem + 32768;            // [8 ds][4 b][128 jl]
    float* hb  = smem + 32768 + 4096;     // [2][4 b][256 d]

    int tid = threadIdx.x;
    uint32_t rank = ctarank();
    int cid = blockIdx.x >> 3;
    int b0 = cid * BPC;
    int wid = tid >> 5, lane = tid & 31;

    // ---- prologue: load 128 weight rows, transposed into wsm --------------
    {
        int jl = tid & 127, dh = tid >> 7;
        int jglob = (jl >> 5) * 256 + 32 * (int)rank + (jl & 31);
        const float* wrow = w_hh + (size_t)jglob * DD;
#pragma unroll 4
        for (int it = 0; it < 32; it++) {
            int d = dh * 128 + it * 4;
            float4 v = *(const float4*)(wrow + d);
            wsm[(d + 0) * 128 + jl] = v.x;
            wsm[(d + 1) * 128 + jl] = v.y;
            wsm[(d + 2) * 128 + jl] = v.z;
            wsm[(d + 3) * 128 + jl] = v.w;
        }
    }
    for (int i = tid; i < 2048; i += 256) hb[i] = 0.f;
    __syncthreads();
    cluster_sync();

    int actb = tid >> 5;        // for tid<128: batch 0..3
    int actd = tid & 31;        // local d
    float c_reg = 0.f;
    int dglob = 32 * (int)rank + actd;
    uint32_t hloc_base = (uint32_t)__cvta_generic_to_shared(hb);

    for (int t = 0; t < TT; t++) {
        const float* hcur = hb + (t & 1) * 1024;

        // prefetch gate pre-activations for this step (used after reduce)
        float xg0 = 0.f, xg1 = 0.f, xg2 = 0.f, xg3 = 0.f;
        if (tid < 128) {
            const float* xp = d_xs + ((size_t)(b0 + actb) * TT + t) * GG + dglob;
            xg0 = xp[0]; xg1 = xp[256]; xg2 = xp[512]; xg3 = xp[768];
        }

        // ---- compute: warp w covers d in [32w,32w+32); lane owns 4 j's ----
        float acc[4][4];   // [j][b]
#pragma unroll
        for (int j = 0; j < 4; j++)
#pragma unroll
            for (int b = 0; b < 4; b++) acc[j][b] = 0.f;

        const float* wp = wsm + (wid * 32) * 128 + lane * 4;
        const float* hp = hcur + wid * 32;
#pragma unroll
        for (int i4 = 0; i4 < 8; i4++) {
            float wa[4][4];   // [k][j]
            *(float4*)wa[0] = *(const float4*)(wp + 0 * 128);
            *(float4*)wa[1] = *(const float4*)(wp + 1 * 128);
            *(float4*)wa[2] = *(const float4*)(wp + 2 * 128);
            *(float4*)wa[3] = *(const float4*)(wp + 3 * 128);
            float ha[4][4];   // [b][k]
            *(float4*)ha[0] = *(const float4*)(hp + 0);
            *(float4*)ha[1] = *(const float4*)(hp + 256);
            *(float4*)ha[2] = *(const float4*)(hp + 512);
            *(float4*)ha[3] = *(const float4*)(hp + 768);
#pragma unroll
            for (int k = 0; k < 4; k++)
#pragma unroll
                for (int j = 0; j < 4; j++)
#pragma unroll
                    for (int b = 0; b < 4; b++)
                        acc[j][b] += wa[k][j] * ha[b][k];
            wp += 4 * 128;
            hp += 4;
        }
        // partials: psm[wid][b][lane*4..+4]
#pragma unroll
        for (int b = 0; b < 4; b++) {
            float4 v = make_float4(acc[0][b], acc[1][b], acc[2][b], acc[3][b]);
            *(float4*)(psm + ((wid * 4 + b) * 128) + lane * 4) = v;
        }
        __syncthreads();

        // ---- reduce + activations: thread (b,dl) for tid<128 --------------
        if (tid < 128) {
            float g[4] = {xg0, xg1, xg2, xg3};
#pragma unroll
            for (int gma = 0; gma < 4; gma++) {
                int jl = gma * 32 + actd;
                float s = 0.f;
#pragma unroll
                for (int ds = 0; ds < 8; ds++)
                    s += psm[(ds * 4 + actb) * 128 + jl];
                g[gma] += s;
            }
            float ig = sigf(g[0]);
            float fg = sigf(g[1]);
            float gg = tanhf(g[2]);
            float og = sigf(g[3]);
            c_reg = fg * c_reg + ig * gg;
            float hval = og * tanhf(c_reg);
            d_h[((size_t)(b0 + actb) * TT + t) * DD + dglob] = hval;

            // push into every cluster CTA's next-step buffer (incl. self)
            if (t + 1 < TT) {
                uint32_t loff = hloc_base +
                    (uint32_t)((((t + 1) & 1) * 1024 + actb * 256 + dglob) * 4);
#pragma unroll
                for (int r = 0; r < CLS; r++)
                    sts_cluster(mapa_sh(loff, (uint32_t)r), hval);
            }
        }
        cluster_sync();
    }
}

// ---- correlation m + Y = tanh(m@W_y) + z = Y . w_t  (fused) ----------------
__global__ void __launch_bounds__(256) k_att(const float* __restrict__ W_y,
                                             const float* __restrict__ w_t) {
    int b = blockIdx.x;
    int t0 = blockIdx.y * 32;
    int tid = threadIdx.x;
    __shared__ float sdup[2 * DD];
    __shared__ float buf[32][DD];
    __shared__ float zpart[8][32];

    sdup[tid] = d_snorm[b * DD + tid];
    sdup[DD + tid] = d_snorm[b * DD + tid];
    for (int r = 0; r < 32; r++)
        buf[r][tid] = d_h[((size_t)b * TT + t0 + r) * DD + tid];
    __syncthreads();

    float mm[32];
#pragma unroll
    for (int r = 0; r < 32; r++) mm[r] = 0.f;
    for (int d = 0; d < DD; d++) {
        float sv = sdup[d + tid];
#pragma unroll
        for (int r = 0; r < 32; r++) mm[r] += buf[r][d] * sv;
    }
    __syncthreads();
#pragma unroll
    for (int r = 0; r < 32; r++) buf[r][tid] = mm[r];
    __syncthreads();

    float wt = w_t[tid];
#pragma unroll
    for (int r = 0; r < 32; r++) mm[r] = 0.f;
    for (int d = 0; d < DD; d++) {
        float w = W_y[d * DD + tid];
#pragma unroll
        for (int r = 0; r < 32; r++) mm[r] += buf[r][d] * w;
    }
    int lane = tid & 31, wrp = tid >> 5;
#pragma unroll
    for (int r = 0; r < 32; r++) {
        float v = tanhf(mm[r]) * wt;
        v += __shfl_down_sync(0xffffffffu, v, 16);
        v += __shfl_down_sync(0xffffffffu, v, 8);
        v += __shfl_down_sync(0xffffffffu, v, 4);
        v += __shfl_down_sync(0xffffffffu, v, 2);
        v += __shfl_down_sync(0xffffffffu, v, 1);
        if (lane == 0) zpart[wrp][r] = v;
    }
    __syncthreads();
    if (tid < 32) {
        float sacc = 0.f;
#pragma unroll
        for (int w = 0; w < 8; w++) sacc += zpart[w][tid];
        d_z[b * TT + t0 + tid] = sacc;
    }
}

// ---- softmax over T and r = sum_t a[t]*h[t]  --------------------------------
__global__ void __launch_bounds__(256) k_soft_r() {
    int b = blockIdx.x, tid = threadIdx.x;
    __shared__ float zsh[TT];
    __shared__ float red[256];
    zsh[tid] = d_z[b * TT + tid];
    zsh[256 + tid] = d_z[b * TT + 256 + tid];
    __syncthreads();
    float lm = fmaxf(zsh[tid], zsh[tid + 256]);
    red[tid] = lm; __syncthreads();
    for (int s = 128; s > 0; s >>= 1) {
        if (tid < s) red[tid] = fmaxf(red[tid], red[tid + s]);
        __syncthreads();
    }
    float mx = red[0]; __syncthreads();
    float e0 = expf(zsh[tid] - mx), e1 = expf(zsh[tid + 256] - mx);
    red[tid] = e0 + e1; __syncthreads();
    for (int s = 128; s > 0; s >>= 1) {
        if (tid < s) red[tid] += red[tid + s];
        __syncthreads();
    }
    float inv = 1.f / red[0]; __syncthreads();
    zsh[tid] = e0 * inv;
    zsh[tid + 256] = e1 * inv;
    __syncthreads();
    float acc = 0.f;
    const float* hbp = d_h + (size_t)b * TT * DD;
    for (int t = 0; t < TT; t++) acc += zsh[t] * hbp[(size_t)t * DD + tid];
    d_r[b * DD + tid] = acc;
}

// ---- final head -------------------------------------------------------------
__global__ void __launch_bounds__(256) k_final(const float* __restrict__ b_f,
                                               float* __restrict__ out) {
    int b = blockIdx.x, tid = threadIdx.x;
    __shared__ float rsh[DD], hls[DD], rrsh[DD], red[256];
    rsh[tid] = d_r[b * DD + tid];
    hls[tid] = d_h[((size_t)b * TT + (TT - 1)) * DD + tid];
    __syncthreads();
    float acc = 0.f;
    for (int d = 0; d < DD; d++)
        acc += rsh[d] * d_WpT[d * DD + tid] + hls[d] * d_WxT[d * DD + tid];
    rrsh[tid] = tanhf(acc);
    __syncthreads();
    float lg = b_f[tid];
    for (int e = 0; e < DD; e++) lg += rrsh[e] * d_WfT[e * DD + tid];
    red[tid] = lg; __syncthreads();
    for (int s = 128; s > 0; s >>= 1) {
        if (tid < s) red[tid] = fmaxf(red[tid], red[tid + s]);
        __syncthreads();
    }
    float mx = red[0]; __syncthreads();
    float ex = expf(lg - mx);
    red[tid] = ex; __syncthreads();
    for (int s = 128; s > 0; s >>= 1) {
        if (tid < s) red[tid] += red[tid + s];
        __syncthreads();
    }
    out[b * DD + tid] = ex / red[0];
}

// ---------------------------------------------------------------------------
extern "C" void kernel_launch(void* const* d_in, const int* in_sizes, int n_in,
                              void* d_out, int out_size) {
    const int*   x      = (const int*)d_in[0];
    const int*   s      = (const int*)d_in[1];
    const float* emb    = (const float*)d_in[2];
    const float* w_ih   = (const float*)d_in[3];
    const float* w_hh   = (const float*)d_in[4];
    const float* b_lstm = (const float*)d_in[5];
    const float* W_y    = (const float*)d_in[6];
    const float* w_t    = (const float*)d_in[7];
    const float* W_p    = (const float*)d_in[8];
    const float* W_x    = (const float*)d_in[9];
    const float* W_f    = (const float*)d_in[10];
    const float* b_f    = (const float*)d_in[11];
    float* out = (float*)d_out;

    const size_t lstm_smem = (32768 + 4096 + 2048) * sizeof(float);
    cudaFuncSetAttribute(k_lstm2, cudaFuncAttributeMaxDynamicSharedMemorySize,
                         (int)lstm_smem);

    k_prep<<<256, 256>>>(W_p, W_x, W_f);
    k_snorm<<<1, 256>>>(s, emb);
    k_xs<<<dim3(512, 16), 256>>>(x, emb, w_ih, b_lstm);
    k_lstm2<<<128, 256, lstm_smem>>>(w_hh);
    k_att<<<dim3(64, 16), 256>>>(W_y, w_t);
    k_soft_r<<<64, 256>>>();
    k_final<<<64, 256>>>(b_f, out);
}

// round 4
// speedup vs baseline: 4.9409x; 1.1782x over previous
#include <cuda_runtime.h>
#include <cstdint>
#include <cstddef>

typedef unsigned long long u64;

#define BB 64
#define TT 512
#define DD 256
#define GG 1024   // 4*D
#define CLS 8     // CTAs per cluster
#define BPC 4     // batches per cluster

// ---------------- scratch (device globals; no runtime allocation) ----------
__device__ float d_xs[(size_t)BB * TT * GG];
__device__ float d_h[(size_t)BB * TT * DD];
__device__ float d_snorm[BB * DD];
__device__ float d_WpT[DD * DD];
__device__ float d_WxT[DD * DD];
__device__ float d_WfT[DD * DD];
__device__ float d_z[BB * TT];
__device__ float d_rp[BB * 8 * DD];

__device__ __forceinline__ float sigf(float x) { return 1.f / (1.f + expf(-x)); }

__device__ __forceinline__ uint32_t ctarank() {
    uint32_t r; asm("mov.u32 %0, %%cluster_ctarank;" : "=r"(r)); return r;
}
__device__ __forceinline__ void cluster_sync() {
    asm volatile("barrier.cluster.arrive.aligned;\n\tbarrier.cluster.wait.aligned;" ::: "memory");
}
__device__ __forceinline__ uint32_t mapa_sh(uint32_t laddr, uint32_t rank) {
    uint32_t ra; asm("mapa.shared::cluster.u32 %0, %1, %2;" : "=r"(ra) : "r"(laddr), "r"(rank));
    return ra;
}
__device__ __forceinline__ void sts_cluster(uint32_t raddr, float v) {
    asm volatile("st.shared::cluster.f32 [%0], %1;" :: "r"(raddr), "f"(v) : "memory");
}

// ---------------- packed f32x2 helpers --------------------------------------
__device__ __forceinline__ u64 dup2(float v) {
    u64 r; asm("mov.b64 %0, {%1, %1};" : "=l"(r) : "f"(v)); return r;
}
__device__ __forceinline__ void fma2(u64& d, u64 a, u64 b) {
    asm("fma.rn.f32x2 %0, %1, %2, %0;" : "+l"(d) : "l"(a), "l"(b));
}
__device__ __forceinline__ void up2(float& lo, float& hi, u64 v) {
    asm("mov.b64 {%0, %1}, %2;" : "=f"(lo), "=f"(hi) : "l"(v));
}

// ---------------- prep: transposes for coalesced access --------------------
__global__ void k_prep(const float* __restrict__ W_p,
                       const float* __restrict__ W_x, const float* __restrict__ W_f) {
    int i = blockIdx.x * 256 + threadIdx.x;
    if (i < DD * DD) {
        int e = i / DD, d = i % DD;
        d_WpT[d * DD + e] = W_p[i];
        d_WxT[d * DD + e] = W_x[i];
        d_WfT[d * DD + e] = W_f[i];
    }
}

// ---------------- s_norm: batch-norm of query embeddings --------------------
__global__ void k_snorm(const int* __restrict__ s, const float* __restrict__ emb) {
    int d = threadIdx.x;  // 256 threads
    float sum = 0.f, sq = 0.f;
    for (int b = 0; b < BB; b++) {
        float v = emb[(size_t)s[b] * DD + d];
        sum += v; sq += v * v;
    }
    float mu  = sum * (1.f / BB);
    float var = sq * (1.f / BB) - mu * mu;
    float inv = rsqrtf(var + 1e-5f);
    for (int b = 0; b < BB; b++) {
        float v = emb[(size_t)s[b] * DD + d];
        d_snorm[b * DD + d] = (v - mu) * inv;
    }
}

// ---------------- xs = emb[x] @ w_ih.T + b_lstm  (gather GEMM, f32x2) -------
__global__ void __launch_bounds__(256) k_xs(const int* __restrict__ x,
                                            const float* __restrict__ emb,
                                            const float* __restrict__ w_ih,
                                            const float* __restrict__ bl) {
    __shared__ float As[16][64];
    __shared__ float Bs[16][64];
    int tid = threadIdx.x;
    int m0 = blockIdx.x * 64, n0 = blockIdx.y * 64;
    int tx = tid % 16, ty = tid / 16;
    int lr = tid / 4, lk = (tid % 4) * 4;

    int tok = x[m0 + lr];
    const float* arow = emb + (size_t)tok * DD;
    const float* brow = w_ih + (size_t)(n0 + lr) * DD;

    u64 acc2[4][2];
#pragma unroll
    for (int i = 0; i < 4; i++) { acc2[i][0] = 0ull; acc2[i][1] = 0ull; }

    for (int k0 = 0; k0 < DD; k0 += 16) {
        float4 av = *(const float4*)(arow + k0 + lk);
        float4 bv = *(const float4*)(brow + k0 + lk);
        As[lk + 0][lr] = av.x; As[lk + 1][lr] = av.y;
        As[lk + 2][lr] = av.z; As[lk + 3][lr] = av.w;
        Bs[lk + 0][lr] = bv.x; Bs[lk + 1][lr] = bv.y;
        Bs[lk + 2][lr] = bv.z; Bs[lk + 3][lr] = bv.w;
        __syncthreads();
#pragma unroll
        for (int k = 0; k < 16; k++) {
            float4 a = *(const float4*)&As[k][ty * 4];
            const u64* bp = (const u64*)&Bs[k][tx * 4];
            u64 b0 = bp[0], b1 = bp[1];
            float aa[4] = {a.x, a.y, a.z, a.w};
#pragma unroll
            for (int i = 0; i < 4; i++) {
                u64 ai = dup2(aa[i]);
                fma2(acc2[i][0], ai, b0);
                fma2(acc2[i][1], ai, b1);
            }
        }
        __syncthreads();
    }
#pragma unroll
    for (int i = 0; i < 4; i++) {
        size_t row = m0 + ty * 4 + i;
        float c0, c1, c2, c3;
        up2(c0, c1, acc2[i][0]);
        up2(c2, c3, acc2[i][1]);
        int col = n0 + tx * 4;
        float* op = d_xs + row * GG + col;
        op[0] = c0 + bl[col + 0];
        op[1] = c1 + bl[col + 1];
        op[2] = c2 + bl[col + 2];
        op[3] = c3 + bl[col + 3];
    }
}

// ---------------- LSTM recurrence: cluster-parallel, reg-weights, f32x2 -----
// 16 clusters x 8 CTAs. Cluster c owns batches [4c,4c+4). CTA rank r owns
// d-slice [32r,32r+32) => gate rows {g*256+32r+i}. Weights register-resident.
__global__ void __launch_bounds__(256, 1) __cluster_dims__(CLS, 1, 1)
k_lstm2(const float* __restrict__ w_hh) {
    extern __shared__ float smem[];
    float* wsm = smem;                    // [256 d][128 jl]   (staging only)
    float* psm = smem + 32768;            // [8 ds][4 b][128 jl]
    float* hb  = smem + 32768 + 4096;     // [2][4 b][256 d]

    int tid = threadIdx.x;
    uint32_t rank = ctarank();
    int b0 = (blockIdx.x >> 3) * BPC;
    int wid = tid >> 5, lane = tid & 31;

    // ---- stage weights (coalesced) into wsm --------------------------------
    {
        int jl = tid & 127, dh = tid >> 7;
        int jglob = (jl >> 5) * 256 + 32 * (int)rank + (jl & 31);
        const float* wrow = w_hh + (size_t)jglob * DD;
#pragma unroll 4
        for (int it = 0; it < 32; it++) {
            int d = dh * 128 + it * 4;
            float4 v = *(const float4*)(wrow + d);
            wsm[(d + 0) * 128 + jl] = v.x;
            wsm[(d + 1) * 128 + jl] = v.y;
            wsm[(d + 2) * 128 + jl] = v.z;
            wsm[(d + 3) * 128 + jl] = v.w;
        }
    }
    for (int i = tid; i < 2048; i += 256) hb[i] = 0.f;
    __syncthreads();

    // ---- weights -> registers as f32x2 pairs (j0,j1),(j2,j3) ---------------
    u64 wreg[8][4][2];
#pragma unroll
    for (int i4 = 0; i4 < 8; i4++)
#pragma unroll
        for (int k = 0; k < 4; k++) {
            const u64* wp2 = (const u64*)(wsm + (wid * 32 + i4 * 4 + k) * 128 + lane * 4);
            wreg[i4][k][0] = wp2[0];
            wreg[i4][k][1] = wp2[1];
        }
    cluster_sync();

    int actb = tid >> 5;        // for tid<128: batch 0..3
    int actd = tid & 31;        // local d
    float c_reg = 0.f;
    int dglob = 32 * (int)rank + actd;
    uint32_t hloc = (uint32_t)__cvta_generic_to_shared(hb);

    // pre-map push addresses (buffer 0 slot); buffer-1 = +4096 bytes
    uint32_t paddr[CLS];
    if (tid < 128) {
        uint32_t l0 = hloc + (uint32_t)((actb * 256 + dglob) * 4);
#pragma unroll
        for (int r = 0; r < CLS; r++) paddr[r] = mapa_sh(l0, (uint32_t)r);
    }

    for (int t = 0; t < TT; t++) {
        const float* hcur = hb + (t & 1) * 1024;

        float xg0 = 0.f, xg1 = 0.f, xg2 = 0.f, xg3 = 0.f;
        if (tid < 128) {
            const float* xp = d_xs + ((size_t)(b0 + actb) * TT + t) * GG + dglob;
            xg0 = xp[0]; xg1 = xp[256]; xg2 = xp[512]; xg3 = xp[768];
        }

        u64 acc2[2][4];
#pragma unroll
        for (int b = 0; b < 4; b++) { acc2[0][b] = 0ull; acc2[1][b] = 0ull; }

        const float* hp = hcur + wid * 32;
#pragma unroll
        for (int i4 = 0; i4 < 8; i4++) {
            float ha[4][4];   // [b][k]
            *(float4*)ha[0] = *(const float4*)(hp + 0);
            *(float4*)ha[1] = *(const float4*)(hp + 256);
            *(float4*)ha[2] = *(const float4*)(hp + 512);
            *(float4*)ha[3] = *(const float4*)(hp + 768);
#pragma unroll
            for (int k = 0; k < 4; k++)
#pragma unroll
                for (int b = 0; b < 4; b++) {
                    u64 hh = dup2(ha[b][k]);
                    fma2(acc2[0][b], wreg[i4][k][0], hh);
                    fma2(acc2[1][b], wreg[i4][k][1], hh);
                }
            hp += 4;
        }
#pragma unroll
        for (int b = 0; b < 4; b++) {
            float x0, x1, x2, x3;
            up2(x0, x1, acc2[0][b]);
            up2(x2, x3, acc2[1][b]);
            *(float4*)(psm + (wid * 4 + b) * 128 + lane * 4) = make_float4(x0, x1, x2, x3);
        }
        __syncthreads();

        if (tid < 128) {
            float g[4] = {xg0, xg1, xg2, xg3};
#pragma unroll
            for (int gm = 0; gm < 4; gm++) {
                int jl = gm * 32 + actd;
                float s = 0.f;
#pragma unroll
                for (int ds = 0; ds < 8; ds++)
                    s += psm[(ds * 4 + actb) * 128 + jl];
                g[gm] += s;
            }
            float ig = sigf(g[0]);
            float fg = sigf(g[1]);
            float gg = tanhf(g[2]);
            float og = sigf(g[3]);
            c_reg = fg * c_reg + ig * gg;
            float hval = og * tanhf(c_reg);
            d_h[((size_t)(b0 + actb) * TT + t) * DD + dglob] = hval;

            if (t + 1 < TT) {
                uint32_t off = (uint32_t)(((t + 1) & 1) * 4096);
#pragma unroll
                for (int r = 0; r < CLS; r++)
                    sts_cluster(paddr[r] + off, hval);
            }
        }
        cluster_sync();
    }
}

// ---- correlation m + Y = tanh(m@W_y) + z = Y . w_t  (fused, f32x2) ---------
// grid (b=64, tblk=16): CTA handles 32 timesteps of one batch element.
// Transposed SMEM tiles (stride 36) give natural (r,r+1) f32x2 pairs.
__global__ void __launch_bounds__(256) k_att(const float* __restrict__ W_y,
                                             const float* __restrict__ w_t) {
    extern __shared__ float sm[];
    float* sdup = sm;               // 512
    float* bufT = sm + 512;         // [256 d][36] (32 used)
    float* mT   = sm + 512 + 9216;  // [256 d][36]
    float* zp   = sm + 512 + 18432; // [8][32]

    int b = blockIdx.x;
    int t0 = blockIdx.y * 32;
    int tid = threadIdx.x;

    float sv0 = d_snorm[b * DD + tid];
    sdup[tid] = sv0;
    sdup[DD + tid] = sv0;

    // bufT[d=tid][r] = h[t0+r][tid]
    const float* hrow = d_h + ((size_t)b * TT + t0) * DD + tid;
#pragma unroll 4
    for (int r = 0; r < 32; r++)
        bufT[tid * 36 + r] = hrow[(size_t)r * DD];
    __syncthreads();

    // stage 1: m[r][n=tid] = sum_d h[r][d] * s_norm[(d+n)%D], r-pairs packed
    u64 mm2[16];
#pragma unroll
    for (int r2 = 0; r2 < 16; r2++) mm2[r2] = 0ull;
#pragma unroll 2
    for (int d = 0; d < DD; d++) {
        u64 s2 = dup2(sdup[d + tid]);
        const u64* bp = (const u64*)(bufT + d * 36);
#pragma unroll
        for (int r2 = 0; r2 < 16; r2++) fma2(mm2[r2], bp[r2], s2);
    }

    // transpose store: mT[n=tid][r-pairs]
    {
        u64* mtp = (u64*)(mT + tid * 36);
#pragma unroll
        for (int r2 = 0; r2 < 16; r2++) mtp[r2] = mm2[r2];
    }
    __syncthreads();

    // stage 2: Y[r][e=tid] = sum_d m[r][d] * W_y[d][e]
    u64 yy2[16];
#pragma unroll
    for (int r2 = 0; r2 < 16; r2++) yy2[r2] = 0ull;
    for (int d = 0; d < DD; d += 4) {
        float w0 = W_y[(d + 0) * DD + tid];
        float w1 = W_y[(d + 1) * DD + tid];
        float w2 = W_y[(d + 2) * DD + tid];
        float w3 = W_y[(d + 3) * DD + tid];
        u64 wd0 = dup2(w0), wd1 = dup2(w1), wd2 = dup2(w2), wd3 = dup2(w3);
        const u64* mp0 = (const u64*)(mT + (d + 0) * 36);
        const u64* mp1 = (const u64*)(mT + (d + 1) * 36);
        const u64* mp2 = (const u64*)(mT + (d + 2) * 36);
        const u64* mp3 = (const u64*)(mT + (d + 3) * 36);
#pragma unroll
        for (int r2 = 0; r2 < 16; r2++) {
            fma2(yy2[r2], mp0[r2], wd0);
            fma2(yy2[r2], mp1[r2], wd1);
            fma2(yy2[r2], mp2[r2], wd2);
            fma2(yy2[r2], mp3[r2], wd3);
        }
    }

    float y[32];
#pragma unroll
    for (int r2 = 0; r2 < 16; r2++) up2(y[2 * r2], y[2 * r2 + 1], yy2[r2]);

    float wt = w_t[tid];
    int lane = tid & 31, wrp = tid >> 5;
#pragma unroll
    for (int r = 0; r < 32; r++) {
        float v = tanhf(y[r]) * wt;
        v += __shfl_down_sync(0xffffffffu, v, 16);
        v += __shfl_down_sync(0xffffffffu, v, 8);
        v += __shfl_down_sync(0xffffffffu, v, 4);
        v += __shfl_down_sync(0xffffffffu, v, 2);
        v += __shfl_down_sync(0xffffffffu, v, 1);
        if (lane == 0) zp[wrp * 32 + r] = v;
    }
    __syncthreads();
    if (tid < 32) {
        float sacc = 0.f;
#pragma unroll
        for (int w = 0; w < 8; w++) sacc += zp[w * 32 + tid];
        d_z[b * TT + t0 + tid] = sacc;
    }
}

// ---- softmax over T (writes normalized a back into d_z) --------------------
__global__ void __launch_bounds__(256) k_soft() {
    int b = blockIdx.x, tid = threadIdx.x;
    __shared__ float zsh[TT];
    __shared__ float red[256];
    zsh[tid] = d_z[b * TT + tid];
    zsh[256 + tid] = d_z[b * TT + 256 + tid];
    __syncthreads();
    float lm = fmaxf(zsh[tid], zsh[tid + 256]);
    red[tid] = lm; __syncthreads();
    for (int s = 128; s > 0; s >>= 1) {
        if (tid < s) red[tid] = fmaxf(red[tid], red[tid + s]);
        __syncthreads();
    }
    float mx = red[0]; __syncthreads();
    float e0 = expf(zsh[tid] - mx), e1 = expf(zsh[tid + 256] - mx);
    red[tid] = e0 + e1; __syncthreads();
    for (int s = 128; s > 0; s >>= 1) {
        if (tid < s) red[tid] += red[tid + s];
        __syncthreads();
    }
    float inv = 1.f / red[0];
    d_z[b * TT + tid] = e0 * inv;
    d_z[b * TT + 256 + tid] = e1 * inv;
}

// ---- partial r: grid (64, 8), each CTA sums 64 timesteps -------------------
__global__ void __launch_bounds__(256) k_rpart() {
    int b = blockIdx.x, q = blockIdx.y, tid = threadIdx.x;
    const float* hbp = d_h + ((size_t)b * TT + q * 64) * DD + tid;
    const float* ap  = d_z + b * TT + q * 64;
    float acc = 0.f;
#pragma unroll 8
    for (int t = 0; t < 64; t++)
        acc += ap[t] * hbp[(size_t)t * DD];
    d_rp[(b * 8 + q) * DD + tid] = acc;
}

// ---- final head -------------------------------------------------------------
__global__ void __launch_bounds__(256) k_final(const float* __restrict__ b_f,
                                               float* __restrict__ out) {
    int b = blockIdx.x, tid = threadIdx.x;
    __shared__ float rsh[DD], hls[DD], rrsh[DD], red[256];
    float racc = 0.f;
#pragma unroll
    for (int q = 0; q < 8; q++) racc += d_rp[(b * 8 + q) * DD + tid];
    rsh[tid] = racc;
    hls[tid] = d_h[((size_t)b * TT + (TT - 1)) * DD + tid];
    __syncthreads();
    float acc = 0.f;
    for (int d = 0; d < DD; d++)
        acc += rsh[d] * d_WpT[d * DD + tid] + hls[d] * d_WxT[d * DD + tid];
    rrsh[tid] = tanhf(acc);
    __syncthreads();
    float lg = b_f[tid];
    for (int e = 0; e < DD; e++) lg += rrsh[e] * d_WfT[e * DD + tid];
    red[tid] = lg; __syncthreads();
    for (int s = 128; s > 0; s >>= 1) {
        if (tid < s) red[tid] = fmaxf(red[tid], red[tid + s]);
        __syncthreads();
    }
    float mx = red[0]; __syncthreads();
    float ex = expf(lg - mx);
    red[tid] = ex; __syncthreads();
    for (int s = 128; s > 0; s >>= 1) {
        if (tid < s) red[tid] += red[tid + s];
        __syncthreads();
    }
    out[b * DD + tid] = ex / red[0];
}

// ---------------------------------------------------------------------------
extern "C" void kernel_launch(void* const* d_in, const int* in_sizes, int n_in,
                              void* d_out, int out_size) {
    const int*   x      = (const int*)d_in[0];
    const int*   s      = (const int*)d_in[1];
    const float* emb    = (const float*)d_in[2];
    const float* w_ih   = (const float*)d_in[3];
    const float* w_hh   = (const float*)d_in[4];
    const float* b_lstm = (const float*)d_in[5];
    const float* W_y    = (const float*)d_in[6];
    const float* w_t    = (const float*)d_in[7];
    const float* W_p    = (const float*)d_in[8];
    const float* W_x    = (const float*)d_in[9];
    const float* W_f    = (const float*)d_in[10];
    const float* b_f    = (const float*)d_in[11];
    float* out = (float*)d_out;

    const size_t lstm_smem = (32768 + 4096 + 2048) * sizeof(float);
    const size_t att_smem  = (512 + 2 * 256 * 36 + 256) * sizeof(float);
    cudaFuncSetAttribute(k_lstm2, cudaFuncAttributeMaxDynamicSharedMemorySize,
                         (int)lstm_smem);
    cudaFuncSetAttribute(k_att, cudaFuncAttributeMaxDynamicSharedMemorySize,
                         (int)att_smem);

    k_prep<<<256, 256>>>(W_p, W_x, W_f);
    k_snorm<<<1, 256>>>(s, emb);
    k_xs<<<dim3(512, 16), 256>>>(x, emb, w_ih, b_lstm);
    k_lstm2<<<128, 256, lstm_smem>>>(w_hh);
    k_att<<<dim3(64, 16), 256, att_smem>>>(W_y, w_t);
    k_soft<<<64, 256>>>();
    k_rpart<<<dim3(64, 8), 256>>>();
    k_final<<<64, 256>>>(b_f, out);
}